// round 17
// baseline (speedup 1.0000x reference)
#include <cuda_runtime.h>
#include <cuda_fp16.h>
#include <math.h>
#include <stdint.h>

#define Bn    2
#define Sn    2048
#define DIN   2048
#define Hn    16
#define Gn    4
#define HD    128
#define DOUT  2048
#define GROUPn 4          // H / G
#define EPSf  1e-6f
#define Mrows (Bn*Sn)     // 4096
#define NQKV  (2*DOUT + 2*Gn*HD)   // 5120 = Wq(4096) | Wk(512) | Wv(512)

// ---------------- scratch (device globals; no allocation allowed) ----------
__device__ __half g_Gate[(size_t)Bn*Sn*Hn*HD];    // [b,s,h,d] fp16 gate

// fp16 attention operands
__device__ __half g_Qh[(size_t)Bn*Hn*Sn*HD];
__device__ __half g_Kh[(size_t)Bn*Gn*Sn*HD];
__device__ __half g_Vh[(size_t)Bn*Gn*Sn*HD];

// fp16 scratch for GEMMs
__device__ __half g_xh [(size_t)Mrows*DIN];
__device__ __half g_Wah[(size_t)NQKV*DIN];   // packed Wq|Wk|Wv, [N][K]
__device__ __half g_Woh[(size_t)DIN*DOUT];
__device__ __half g_Cxh[(size_t)Mrows*DOUT];

// ======================= PTX helpers (compute_103 baseline only) ==========
__device__ __forceinline__ uint32_t smem_u32(const void* p) {
    uint32_t a;
    asm("{ .reg .u64 t; cvta.to.shared.u64 t, %1; cvt.u32.u64 %0, t; }" : "=r"(a) : "l"(p));
    return a;
}
__device__ __forceinline__ void cp16(uint32_t s, const void* g) {
    asm volatile("cp.async.cg.shared.global [%0], [%1], 16;" :: "r"(s), "l"(g));
}
#define CP_COMMIT() asm volatile("cp.async.commit_group;" ::: "memory")
#define CP_WAIT(n)  asm volatile("cp.async.wait_group %0;" :: "n"(n) : "memory")

__device__ __forceinline__ void ldsm_x4(uint32_t* r, uint32_t addr) {
    asm volatile("ldmatrix.sync.aligned.m8n8.x4.shared.b16 {%0,%1,%2,%3}, [%4];"
        : "=r"(r[0]), "=r"(r[1]), "=r"(r[2]), "=r"(r[3]) : "r"(addr));
}
__device__ __forceinline__ void ldsm_x4t(uint32_t* r, uint32_t addr) {
    asm volatile("ldmatrix.sync.aligned.m8n8.x4.trans.shared.b16 {%0,%1,%2,%3}, [%4];"
        : "=r"(r[0]), "=r"(r[1]), "=r"(r[2]), "=r"(r[3]) : "r"(addr));
}
__device__ __forceinline__ void mma16816(float* d, const uint32_t* a, const uint32_t* b) {
    asm volatile(
        "mma.sync.aligned.m16n8k16.row.col.f32.f16.f16.f32 "
        "{%0,%1,%2,%3}, {%4,%5,%6,%7}, {%8,%9}, {%0,%1,%2,%3};"
        : "+f"(d[0]), "+f"(d[1]), "+f"(d[2]), "+f"(d[3])
        : "r"(a[0]), "r"(a[1]), "r"(a[2]), "r"(a[3]), "r"(b[0]), "r"(b[1]));
}
__device__ __forceinline__ float ex2f(float x) {
    float r; asm("ex2.approx.f32 %0, %1;" : "=f"(r) : "f"(x)); return r;
}
__device__ __forceinline__ uint32_t packh2(float lo, float hi) {
    uint32_t r; asm("cvt.rn.f16x2.f32 %0, %1, %2;" : "=r"(r) : "f"(hi), "f"(lo)); return r;
}

// ======================= convert / merged transpose =======================
__global__ __launch_bounds__(256) void fconv(const float* __restrict__ in,
                                             __half* __restrict__ h, int n)
{
    int i = (blockIdx.x * 256 + threadIdx.x) * 4;
    if (i >= n) return;
    float4 v = *(const float4*)(in + i);
    *(__half2*)(h + i)     = __halves2half2(__float2half_rn(v.x), __float2half_rn(v.y));
    *(__half2*)(h + i + 2) = __halves2half2(__float2half_rn(v.z), __float2half_rn(v.w));
}

// all four weights transposed in one launch; blockIdx.x routes.
__global__ __launch_bounds__(256) void tsplit_all(
    const float* __restrict__ Wq, const float* __restrict__ Wk,
    const float* __restrict__ Wv, const float* __restrict__ Wo,
    __half* __restrict__ Wah, __half* __restrict__ Woh)
{
    const int bx = blockIdx.x;
    const float* W; __half* Th; int N, nt;
    if (bx < 128)      { W = Wq; Th = Wah;                                  N = 4096; nt = bx; }
    else if (bx < 144) { W = Wk; Th = Wah + (size_t)(2*DOUT) * DIN;         N = 512;  nt = bx - 128; }
    else if (bx < 160) { W = Wv; Th = Wah + (size_t)(2*DOUT + Gn*HD) * DIN; N = 512;  nt = bx - 144; }
    else               { W = Wo; Th = Woh;                                  N = 2048; nt = bx - 160; }

    __shared__ float t[32][33];
    const int n0 = nt * 32, k0 = blockIdx.y * 32;
    const int tx = threadIdx.x, ty = threadIdx.y;  // (32, 8)
    #pragma unroll
    for (int r = 0; r < 4; r++)
        t[ty + r * 8][tx] = W[(size_t)(k0 + ty + r * 8) * N + n0 + tx];
    __syncthreads();
    #pragma unroll
    for (int r = 0; r < 4; r++) {
        int n = n0 + ty + r * 8, k = k0 + tx;
        Th[(size_t)n * DIN + k] = __float2half_rn(t[tx][ty + r * 8]);
    }
}

// ======================= HMMA 1-term fp16 GEMM (128xNT, 3-stage) ===========
// C = Ah * Bh^T. FUSED=false: write fp32 C0 (stride N0).
// FUSED=true (QKV, NT=128): per-n-tile typed epilogue:
//   Wq even tile -> rmsnorm+rope -> Qh ; Wq odd tile -> fp16 Gate
//   K tiles -> rmsnorm+rope -> Kh ; V tiles -> fp16 Vh
#define GBK    32
#define LDS    40
#define ATILEB (128 * LDS * 2)            // 10240 B
#define GEMM_SMEM (116 * 1024)            // force 1 block/SM

template<int NT, bool FUSED>
__device__ __forceinline__ void load_stage(
    uint32_t smb, int stage,
    const __half* __restrict__ pAh, const __half* __restrict__ pBh,
    int K, int kc, int tid)
{
    const int BTILEB = NT * LDS * 2;
    const int STAGEB = ATILEB + BTILEB;
    const uint32_t sb = smb + stage * STAGEB;
    #pragma unroll
    for (int i = 0; i < 2; i++) {
        const int u = tid + i * 256;
        const int row = u >> 2, col = (u & 3) * 8;
        cp16(sb + (uint32_t)(row * LDS + col) * 2, pAh + (size_t)row * K + kc + col);
    }
    #pragma unroll
    for (int i = 0; i < NT / 64; i++) {
        const int u = tid + i * 256;
        const int row = u >> 2, col = (u & 3) * 8;
        cp16(sb + ATILEB + (uint32_t)(row * LDS + col) * 2, pBh + (size_t)row * K + kc + col);
    }
}

template<int NT, bool FUSED>
__global__ __launch_bounds__(256, 1) void gemm_tc(
    const __half* __restrict__ Ah, const __half* __restrict__ Bh,
    float* __restrict__ C0, int M, int N0, int K,
    __half* __restrict__ Qh, __half* __restrict__ Kh, __half* __restrict__ Vh,
    __half* __restrict__ Gate,
    const float* __restrict__ qw, const float* __restrict__ kw,
    const float* __restrict__ cosT, const float* __restrict__ sinT)
{
    constexpr int NFRAG = NT / 16;        // n16 fragments per block row
    constexpr int WNF   = NFRAG;          // per-warp nf count (= NT/2/8)
    const int BTILEB = NT * LDS * 2;
    const int STAGEB = ATILEB + BTILEB;
    const int OFF_B  = ATILEB;

    extern __shared__ char sm[];
    const uint32_t smb = smem_u32(sm);
    const int tid  = threadIdx.x;
    const int wid  = tid >> 5, lane = tid & 31;
    const int wm   = wid & 3;             // 4 m-warps x 32 rows
    const int wn   = wid >> 2;            // 2 n-warps x NT/2 cols
    const int mbr  = blockIdx.y * 128, nbr = blockIdx.x * NT;

    const __half* pAh = Ah + (size_t)mbr * K;
    const __half* pBh = Bh + (size_t)nbr * K;

    float acc[2][WNF][4];
    #pragma unroll
    for (int i = 0; i < 2; i++)
        #pragma unroll
        for (int j = 0; j < WNF; j++)
            #pragma unroll
            for (int k = 0; k < 4; k++) acc[i][j][k] = 0.f;

    const uint32_t aoff = (uint32_t)((wm * 32 + (lane & 15)) * LDS + ((lane >> 4) * 8)) * 2;
    const uint32_t boff = (uint32_t)((wn * (NT / 2) + (lane & 7) + ((lane >> 4) << 3)) * LDS
                                     + (((lane >> 3) & 1) * 8)) * 2;

    const int NC = K / GBK;
    load_stage<NT, FUSED>(smb, 0, pAh, pBh, K, 0, tid);
    CP_COMMIT();
    load_stage<NT, FUSED>(smb, 1, pAh, pBh, K, GBK, tid);
    CP_COMMIT();

    int st_idx = 0;
    for (int c = 0; c < NC; c++) {
        if (c + 1 < NC) { CP_WAIT(1); } else { CP_WAIT(0); }
        __syncthreads();
        if (c + 2 < NC) {
            int ns = st_idx + 2; if (ns >= 3) ns -= 3;
            load_stage<NT, FUSED>(smb, ns, pAh, pBh, K, (c + 2) * GBK, tid);
            CP_COMMIT();
        }

        const uint32_t st = smb + st_idx * STAGEB;
        #pragma unroll
        for (int ks = 0; ks < 2; ks++) {
            const uint32_t kb = ks * 32;
            uint32_t bh[2 * WNF];
            #pragma unroll
            for (int n16 = 0; n16 < WNF / 2; n16++)
                ldsm_x4(bh + 4 * n16, st + OFF_B + boff + n16 * (16 * LDS * 2) + kb);
            #pragma unroll
            for (int mf = 0; mf < 2; mf++) {
                uint32_t ah[4];
                ldsm_x4(ah, st + aoff + mf * (16 * LDS * 2) + kb);
                #pragma unroll
                for (int nf = 0; nf < WNF; nf++)
                    mma16816(acc[mf][nf], ah, &bh[(nf >> 1) * 4 + (nf & 1) * 2]);
            }
        }
        if (++st_idx == 3) st_idx = 0;
    }

    if (!FUSED) {
        #pragma unroll
        for (int mf = 0; mf < 2; mf++) {
            const int r0 = mbr + wm * 32 + mf * 16 + (lane >> 2);
            #pragma unroll
            for (int nf = 0; nf < WNF; nf++) {
                const int n0 = nbr + wn * (NT / 2) + nf * 8 + (lane & 3) * 2;
                *(float2*)(C0 + (size_t)r0 * N0 + n0)       = make_float2(acc[mf][nf][0], acc[mf][nf][1]);
                *(float2*)(C0 + (size_t)(r0 + 8) * N0 + n0) = make_float2(acc[mf][nf][2], acc[mf][nf][3]);
            }
        }
        return;
    }

    // ---------------- fused QKV epilogue (NT == 128) ----------------
    int type, head;
    if (nbr < 2 * DOUT)                { head = nbr >> 8;                    type = (nbr >> 7) & 1; }
    else if (nbr < 2 * DOUT + Gn * HD) { head = (nbr - 2 * DOUT) >> 7;       type = 2; }
    else                               { head = (nbr - 2 * DOUT - Gn * HD) >> 7; type = 3; }

    __syncthreads();
    float* smf = (float*)sm;        // [128][132]
    #pragma unroll
    for (int mf = 0; mf < 2; mf++) {
        const int r0 = wm * 32 + mf * 16 + (lane >> 2);
        #pragma unroll
        for (int nf = 0; nf < WNF; nf++) {
            const int c0 = wn * (NT / 2) + nf * 8 + (lane & 3) * 2;
            smf[r0 * 132 + c0]           = acc[mf][nf][0];
            smf[r0 * 132 + c0 + 1]       = acc[mf][nf][1];
            smf[(r0 + 8) * 132 + c0]     = acc[mf][nf][2];
            smf[(r0 + 8) * 132 + c0 + 1] = acc[mf][nf][3];
        }
    }
    __syncthreads();

    if (type == 0 || type == 2) {
        const float* w = (type == 0) ? qw : kw;
        const float wv0 = 1.f + w[lane],      wv1 = 1.f + w[lane + 32];
        const float wv2 = 1.f + w[lane + 64], wv3 = 1.f + w[lane + 96];
        __half* base = (type == 0)
            ? Qh + (size_t)head * Sn * HD
            : Kh + (size_t)head * Sn * HD;
        const size_t bstride = (type == 0) ? (size_t)Hn * Sn * HD : (size_t)Gn * Sn * HD;
        for (int rr = 0; rr < 16; rr++) {
            const int r = wid * 16 + rr;
            const int m = mbr + r;
            const int b = m >> 11, s = m & (Sn - 1);
            float v0 = smf[r * 132 + lane],      v1 = smf[r * 132 + lane + 32];
            float v2 = smf[r * 132 + lane + 64], v3 = smf[r * 132 + lane + 96];
            float ss = v0 * v0 + v1 * v1 + v2 * v2 + v3 * v3;
            #pragma unroll
            for (int o = 16; o > 0; o >>= 1) ss += __shfl_xor_sync(0xffffffffu, ss, o);
            const float inv = rsqrtf(ss * (1.0f / HD) + EPSf);
            const float n0 = v0 * inv * wv0, n1 = v1 * inv * wv1;
            const float n2 = v2 * inv * wv2, n3 = v3 * inv * wv3;
            const float* cp = cosT + (size_t)s * HD;
            const float* sp = sinT + (size_t)s * HD;
            const float y0 = n0 * cp[lane]      - n2 * sp[lane];
            const float y1 = n1 * cp[lane + 32] - n3 * sp[lane + 32];
            const float y2 = n2 * cp[lane + 64] + n0 * sp[lane + 64];
            const float y3 = n3 * cp[lane + 96] + n1 * sp[lane + 96];
            __half* dst = base + (size_t)b * bstride + (size_t)s * HD;
            dst[lane]      = __float2half_rn(y0);
            dst[lane + 32] = __float2half_rn(y1);
            dst[lane + 64] = __float2half_rn(y2);
            dst[lane + 96] = __float2half_rn(y3);
        }
    } else {
        for (int i = tid; i < 128 * 128; i += 256) {
            const int r = i >> 7, c = i & 127;
            const int m = mbr + r;
            const int b = m >> 11, s = m & (Sn - 1);
            const __half v = __float2half_rn(smf[r * 132 + c]);
            if (type == 1)
                Gate[((size_t)(b * Sn + s) * Hn + head) * HD + c] = v;
            else
                Vh[((size_t)(b * Gn + head) * Sn + s) * HD + c] = v;
        }
    }
}

// ================= HMMA causal flash attention + sigmoid gate ==============
// BQ=128 (8 warps x m16), BK=64, HD=128. 1-term fp16. Q fragments in regs.
// Heavy blocks first. Gate read fp16. Epilogue writes fp16 Ctx.
#define AT_LDS  136
#define Q_ELE   (128 * AT_LDS)
#define KT_ELE  (64 * AT_LDS)
#define KVSTAGE_ELE (2 * KT_ELE)
#define ATT_SMEM ((Q_ELE + 2 * KVSTAGE_ELE) * 2)   // 104448 bytes
#define CSC 0.12751666806979654f    // (1/sqrt(128)) * log2(e)
#define NEGINF __int_as_float(0xff800000)

__device__ __forceinline__ void kv_load(
    uint32_t smb, int stage,
    const __half* kh, const __half* vh, int tid)
{
    const uint32_t base = smb + (Q_ELE + stage * KVSTAGE_ELE) * 2;
    #pragma unroll
    for (int i = 0; i < 4; i++) {
        int u = tid + i * 256;          // 0..1023
        int til = u >> 9;               // 0: Kh, 1: Vh
        int uu = u & 511;
        int row = uu >> 3, c8 = (uu & 7) * 16;
        uint32_t so = (uint32_t)(row * AT_LDS + c8) * 2;
        const __half* src = til ? vh : kh;
        cp16(base + (uint32_t)til * (KT_ELE * 2) + so, src + (size_t)row * HD + c8);
        cp16(base + (uint32_t)til * (KT_ELE * 2) + so + 16, src + (size_t)row * HD + c8 + 8);
    }
}

__global__ __launch_bounds__(256, 1) void attn_mma(
    const __half* __restrict__ Qh,
    const __half* __restrict__ Kh, const __half* __restrict__ Vh,
    const __half* __restrict__ Gate,
    __half* __restrict__ Cxh)
{
    extern __shared__ __half smem_h[];
    const uint32_t smb = smem_u32(smem_h);
    const int qi = gridDim.x - 1 - blockIdx.x;   // heavy blocks first
    const int h = blockIdx.y, b = blockIdx.z;
    const int g  = h / GROUPn;
    const int tid = threadIdx.x, lane = tid & 31, w = tid >> 5;

    const __half* gQh = Qh + ((size_t)(b * Hn + h) * Sn + (size_t)qi * 128) * HD;
    const __half* gKh = Kh + ((size_t)(b * Gn + g) * Sn) * HD;
    const __half* gVh = Vh + ((size_t)(b * Gn + g) * Sn) * HD;

    #pragma unroll
    for (int i = 0; i < 8; i++) {
        int u = tid + i * 256;
        int row = u >> 4, c8 = (u & 15) * 8;
        *(uint4*)(smem_h + row * AT_LDS + c8) = *(const uint4*)(gQh + (size_t)row * HD + c8);
    }

    float m1s = NEGINF, m2s = NEGINF, l1 = 0.f, l2 = 0.f;
    float oacc[16][4];
    #pragma unroll
    for (int nf = 0; nf < 16; nf++)
        #pragma unroll
        for (int k = 0; k < 4; k++) oacc[nf][k] = 0.f;

    const int r1rel = w * 16 + (lane >> 2);
    const int r1g = qi * 128 + r1rel;
    const int r2g = r1g + 8;

    kv_load(smb, 0, gKh, gVh, tid);
    CP_COMMIT();
    CP_WAIT(0);
    __syncthreads();

    uint32_t qh_fr[8][4];
    #pragma unroll
    for (int kq = 0; kq < 8; kq++) {
        const uint32_t qaddr = smb +
            (uint32_t)((w * 16 + (lane & 15)) * AT_LDS + ((lane >> 4) << 3) + kq * 16) * 2;
        ldsm_x4(qh_fr[kq], qaddr);
    }

    const int ntiles = 2 * qi + 2;
    for (int t = 0; t < ntiles; t++) {
        if (t > 0) {
            CP_WAIT(0);
            __syncthreads();
        }
        if (t + 1 < ntiles) {
            kv_load(smb, (t + 1) & 1,
                    gKh + (size_t)(t + 1) * 64 * HD, gVh + (size_t)(t + 1) * 64 * HD, tid);
            CP_COMMIT();
        }

        const uint32_t kb = smb + (Q_ELE + (t & 1) * KVSTAGE_ELE) * 2;

        float sacc[8][4];
        #pragma unroll
        for (int j = 0; j < 8; j++)
            #pragma unroll
            for (int k = 0; k < 4; k++) sacc[j][k] = 0.f;

        #pragma unroll
        for (int kq = 0; kq < 8; kq++) {
            uint32_t bh[16];
            #pragma unroll
            for (int n16 = 0; n16 < 4; n16++) {
                const uint32_t kaddr = kb +
                    (uint32_t)((n16 * 16 + (lane & 7) + ((lane >> 4) << 3)) * AT_LDS
                               + (((lane >> 3) & 1) << 3) + kq * 16) * 2;
                ldsm_x4(bh + 4 * n16, kaddr);
            }
            #pragma unroll
            for (int n16 = 0; n16 < 4; n16++) {
                mma16816(sacc[2 * n16],     qh_fr[kq], bh + 4 * n16);
                mma16816(sacc[2 * n16 + 1], qh_fr[kq], bh + 4 * n16 + 2);
            }
        }

        const bool needmask = (t >= 2 * qi);
        float mt1 = m1s, mt2 = m2s;
        #pragma unroll
        for (int j = 0; j < 8; j++) {
            const int c0 = t * 64 + j * 8 + (lane & 3) * 2;
            #pragma unroll
            for (int k = 0; k < 4; k++) sacc[j][k] *= CSC;
            if (needmask) {
                if (c0     > r1g) sacc[j][0] = NEGINF;
                if (c0 + 1 > r1g) sacc[j][1] = NEGINF;
                if (c0     > r2g) sacc[j][2] = NEGINF;
                if (c0 + 1 > r2g) sacc[j][3] = NEGINF;
            }
            mt1 = fmaxf(mt1, fmaxf(sacc[j][0], sacc[j][1]));
            mt2 = fmaxf(mt2, fmaxf(sacc[j][2], sacc[j][3]));
        }
        mt1 = fmaxf(mt1, __shfl_xor_sync(0xffffffffu, mt1, 1));
        mt1 = fmaxf(mt1, __shfl_xor_sync(0xffffffffu, mt1, 2));
        mt2 = fmaxf(mt2, __shfl_xor_sync(0xffffffffu, mt2, 1));
        mt2 = fmaxf(mt2, __shfl_xor_sync(0xffffffffu, mt2, 2));
        const float f1 = ex2f(m1s - mt1), f2 = ex2f(m2s - mt2);
        m1s = mt1; m2s = mt2;
        float s1 = 0.f, s2 = 0.f;
        #pragma unroll
        for (int j = 0; j < 8; j++) {
            sacc[j][0] = ex2f(sacc[j][0] - mt1);
            sacc[j][1] = ex2f(sacc[j][1] - mt1);
            sacc[j][2] = ex2f(sacc[j][2] - mt2);
            sacc[j][3] = ex2f(sacc[j][3] - mt2);
            s1 += sacc[j][0] + sacc[j][1];
            s2 += sacc[j][2] + sacc[j][3];
        }
        l1 = l1 * f1 + s1;
        l2 = l2 * f2 + s2;
        #pragma unroll
        for (int nf = 0; nf < 16; nf++) {
            oacc[nf][0] *= f1; oacc[nf][1] *= f1;
            oacc[nf][2] *= f2; oacc[nf][3] *= f2;
        }

        #pragma unroll
        for (int kk = 0; kk < 4; kk++) {
            uint32_t a_h[4];
            #pragma unroll
            for (int half = 0; half < 2; half++) {
                a_h[2 * half]     = packh2(sacc[2 * kk + half][0], sacc[2 * kk + half][1]);
                a_h[2 * half + 1] = packh2(sacc[2 * kk + half][2], sacc[2 * kk + half][3]);
            }
            #pragma unroll
            for (int dp = 0; dp < 4; dp++) {
                uint32_t bvh0[4], bvh1[4];
                const uint32_t va0 = kb + KT_ELE * 2 +
                    (uint32_t)((kk * 16 + (lane & 15)) * AT_LDS + (2 * dp) * 16 + ((lane >> 4) << 3)) * 2;
                const uint32_t va1 = va0 + 32;
                ldsm_x4t(bvh0, va0);
                ldsm_x4t(bvh1, va1);
                mma16816(oacc[4 * dp],     a_h, bvh0);
                mma16816(oacc[4 * dp + 1], a_h, bvh0 + 2);
                mma16816(oacc[4 * dp + 2], a_h, bvh1);
                mma16816(oacc[4 * dp + 3], a_h, bvh1 + 2);
            }
        }
    }

    l1 += __shfl_xor_sync(0xffffffffu, l1, 1);
    l1 += __shfl_xor_sync(0xffffffffu, l1, 2);
    l2 += __shfl_xor_sync(0xffffffffu, l2, 1);
    l2 += __shfl_xor_sync(0xffffffffu, l2, 2);
    const float inv1 = 1.0f / l1, inv2 = 1.0f / l2;
    #pragma unroll
    for (int nf = 0; nf < 16; nf++) {
        const int dim = nf * 8 + (lane & 3) * 2;
        #pragma unroll
        for (int rr = 0; rr < 2; rr++) {
            const int q = rr ? r2g : r1g;
            const float invl = rr ? inv2 : inv1;
            const float a0 = oacc[nf][2 * rr], a1 = oacc[nf][2 * rr + 1];
            const __half2 gt = *(const __half2*)(Gate + ((size_t)(b * Sn + q) * Hn + h) * HD + dim);
            const float g0 = __low2float(gt), g1 = __high2float(gt);
            const float v0 = a0 * invl * (1.0f / (1.0f + expf(-g0)));
            const float v1 = a1 * invl * (1.0f / (1.0f + expf(-g1)));
            *(__half2*)(Cxh + (size_t)(b * Sn + q) * DOUT + h * HD + dim) =
                __halves2half2(__float2half_rn(v0), __float2half_rn(v1));
        }
    }
}

// ---------------------------- launcher -------------------------------------
extern "C" void kernel_launch(void* const* d_in, const int* in_sizes, int n_in,
                              void* d_out, int out_size)
{
    const float* x    = (const float*)d_in[0];
    const float* Wq   = (const float*)d_in[1];
    const float* Wk   = (const float*)d_in[2];
    const float* Wv   = (const float*)d_in[3];
    const float* Wo   = (const float*)d_in[4];
    const float* qw   = (const float*)d_in[5];
    const float* kw   = (const float*)d_in[6];
    const float* cosT = (const float*)d_in[7];
    const float* sinT = (const float*)d_in[8];
    float* out = (float*)d_out;

    __half *Qhp, *Khp, *Vhp, *Gp;
    cudaGetSymbolAddress((void**)&Qhp, g_Qh);
    cudaGetSymbolAddress((void**)&Khp, g_Kh);
    cudaGetSymbolAddress((void**)&Vhp, g_Vh);
    cudaGetSymbolAddress((void**)&Gp,  g_Gate);

    __half *xh, *Wah, *Woh, *Cxh;
    cudaGetSymbolAddress((void**)&xh,  g_xh);
    cudaGetSymbolAddress((void**)&Wah, g_Wah);
    cudaGetSymbolAddress((void**)&Woh, g_Woh);
    cudaGetSymbolAddress((void**)&Cxh, g_Cxh);

    cudaFuncSetAttribute(gemm_tc<128, true>,
                         cudaFuncAttributeMaxDynamicSharedMemorySize, GEMM_SMEM);
    cudaFuncSetAttribute(gemm_tc<64, false>,
                         cudaFuncAttributeMaxDynamicSharedMemorySize, GEMM_SMEM);
    cudaFuncSetAttribute(attn_mma, cudaFuncAttributeMaxDynamicSharedMemorySize, ATT_SMEM);

    const int M = Mrows;          // 4096

    // (1) merged weight transpose; (2) x convert
    tsplit_all<<<dim3(224, DIN / 32), dim3(32, 8)>>>(Wq, Wk, Wv, Wo, Wah, Woh);
    fconv<<<(M * DIN / 4 + 255) / 256, 256>>>(x, xh, M * DIN);

    // (3) merged QKV projection with fused norm/rope/gate epilogue
    gemm_tc<128, true><<<dim3(NQKV / 128, M / 128), 256, GEMM_SMEM>>>(
        xh, Wah, (float*)nullptr, M, NQKV, DIN,
        Qhp, Khp, Vhp, Gp, qw, kw, cosT, sinT);

    // (4) HMMA causal attention + gate
    attn_mma<<<dim3(Sn / 128, Hn, Bn), 256, ATT_SMEM>>>(
        Qhp, Khp, Vhp, Gp, Cxh);

    // (5) output projection (128x64 tiles for wave packing)
    gemm_tc<64, false><<<dim3(DIN / 64, M / 128), 256, GEMM_SMEM>>>(
        Cxh, Woh, out, M, DIN, DIN,
        (__half*)nullptr, (__half*)nullptr, (__half*)nullptr, (__half*)nullptr,
        (const float*)nullptr, (const float*)nullptr,
        (const float*)nullptr, (const float*)nullptr);
}